// round 1
// baseline (speedup 1.0000x reference)
#include <cuda_runtime.h>
#include <cstdint>

#define KNBR 16
#define F_IN 7
#define F_HID 40
#define F_OUT 3
#define H2 (F_HID / 2)          // 20 hidden pairs
#define MSG_PER_THREAD 4        // threads per node = 4
#define BLOCK 256

// ---- f32x2 packed helpers (sm_103a; ptxas never auto-fuses, must be PTX) ----
__device__ __forceinline__ unsigned long long pack2(float lo, float hi) {
    unsigned long long r;
    asm("mov.b64 %0, {%1, %2};" : "=l"(r) : "f"(lo), "f"(hi));
    return r;
}
__device__ __forceinline__ unsigned long long fma2(unsigned long long a,
                                                   unsigned long long b,
                                                   unsigned long long c) {
    unsigned long long d;
    asm("fma.rn.f32x2 %0, %1, %2, %3;" : "=l"(d) : "l"(a), "l"(b), "l"(c));
    return d;
}
__device__ __forceinline__ void unpack2(unsigned long long v, float& lo, float& hi) {
    asm("mov.b64 {%0, %1}, %2;" : "=f"(lo), "=f"(hi) : "l"(v));
}

__global__ __launch_bounds__(BLOCK)
void aggre_mlp_kernel(const float* __restrict__ mailbox,
                      const float* __restrict__ W1,
                      const float* __restrict__ b1,
                      const float* __restrict__ W2,
                      const float* __restrict__ b2,
                      float* __restrict__ out,
                      int n_nodes) {
    // Weights staged in shared memory; pair-reads are 8B-aligned (rows are
    // multiples of 8B: 40*4=160, 40*4=160).
    __shared__ __align__(16) float s_w1[F_IN][F_HID];   // [f][h], pair over h
    __shared__ __align__(16) float s_b1[F_HID];
    __shared__ __align__(16) float s_w2t[F_OUT][F_HID]; // transposed: [o][h]
    __shared__ float s_b2[F_OUT];

    const int tid = threadIdx.x;
    for (int i = tid; i < F_IN * F_HID; i += BLOCK) s_w1[i / F_HID][i % F_HID] = W1[i];
    for (int i = tid; i < F_HID; i += BLOCK)        s_b1[i] = b1[i];
    for (int i = tid; i < F_HID * F_OUT; i += BLOCK) s_w2t[i % F_OUT][i / F_OUT] = W2[i];
    if (tid < F_OUT) s_b2[tid] = b2[tid];
    __syncthreads();

    const long long gt = (long long)blockIdx.x * BLOCK + tid;
    const long long total = (long long)n_nodes * (KNBR / MSG_PER_THREAD);
    if (gt >= total) return;                  // tail is warp-granular (128 | total? guard anyway)

    const long long node = gt >> 2;           // 4 threads per node
    const int sub = (int)(gt & 3);

    // 4 messages * 7 floats = 112B contiguous, 16B-aligned (112 = 7*16).
    const float4* src = reinterpret_cast<const float4*>(
        mailbox + (node * KNBR + (long long)sub * MSG_PER_THREAD) * F_IN);

    // Load 28 floats via 7x LDG.128, duplicate each into both halves of an f32x2.
    unsigned long long m2[MSG_PER_THREAD * F_IN];
    #pragma unroll
    for (int i = 0; i < 7; i++) {
        float4 v = src[i];
        m2[i * 4 + 0] = pack2(v.x, v.x);
        m2[i * 4 + 1] = pack2(v.y, v.y);
        m2[i * 4 + 2] = pack2(v.z, v.z);
        m2[i * 4 + 3] = pack2(v.w, v.w);
    }

    float y0 = 0.f, y1 = 0.f, y2 = 0.f;       // partial output over this thread's 4 msgs

    #pragma unroll
    for (int h2 = 0; h2 < H2; h2++) {
        // Broadcast weight pair loads (LDS.64, conflict-free broadcast).
        unsigned long long w[F_IN];
        #pragma unroll
        for (int f = 0; f < F_IN; f++)
            w[f] = *reinterpret_cast<const unsigned long long*>(&s_w1[f][2 * h2]);
        const unsigned long long bp =
            *reinterpret_cast<const unsigned long long*>(&s_b1[2 * h2]);

        float hl = 0.f, hh = 0.f;             // sum over 4 msgs of relu(h pair)
        #pragma unroll
        for (int msg = 0; msg < MSG_PER_THREAD; msg++) {
            unsigned long long acc = bp;
            #pragma unroll
            for (int f = 0; f < F_IN; f++)
                acc = fma2(m2[msg * F_IN + f], w[f], acc);
            float lo, hi;
            unpack2(acc, lo, hi);
            hl += fmaxf(lo, 0.f);
            hh += fmaxf(hi, 0.f);
        }

        // Layer 2 folded through the mean (linear): y_o += hl*W2[2h2][o] + hh*W2[2h2+1][o]
        const float2 wp0 = *reinterpret_cast<const float2*>(&s_w2t[0][2 * h2]);
        const float2 wp1 = *reinterpret_cast<const float2*>(&s_w2t[1][2 * h2]);
        const float2 wp2 = *reinterpret_cast<const float2*>(&s_w2t[2][2 * h2]);
        y0 = fmaf(hl, wp0.x, fmaf(hh, wp0.y, y0));
        y1 = fmaf(hl, wp1.x, fmaf(hh, wp1.y, y1));
        y2 = fmaf(hl, wp2.x, fmaf(hh, wp2.y, y2));
    }

    // Reduce over the 4 sibling lanes of this node (lanes sub=0..3 are adjacent).
    #pragma unroll
    for (int d = 1; d < MSG_PER_THREAD; d <<= 1) {
        y0 += __shfl_xor_sync(0xffffffffu, y0, d);
        y1 += __shfl_xor_sync(0xffffffffu, y1, d);
        y2 += __shfl_xor_sync(0xffffffffu, y2, d);
    }

    if (sub == 0) {
        const float inv = 1.0f / (float)KNBR;
        float* o = out + node * F_OUT;
        o[0] = y0 * inv + s_b2[0];
        o[1] = y1 * inv + s_b2[1];
        o[2] = y2 * inv + s_b2[2];
    }
}

extern "C" void kernel_launch(void* const* d_in, const int* in_sizes, int n_in,
                              void* d_out, int out_size) {
    const float* mailbox = (const float*)d_in[0];
    const float* W1      = (const float*)d_in[1];
    const float* b1      = (const float*)d_in[2];
    const float* W2      = (const float*)d_in[3];
    const float* b2      = (const float*)d_in[4];
    float* out = (float*)d_out;

    const int n_nodes = in_sizes[0] / (KNBR * F_IN);
    const long long total_threads = (long long)n_nodes * (KNBR / MSG_PER_THREAD);
    const int blocks = (int)((total_threads + BLOCK - 1) / BLOCK);

    aggre_mlp_kernel<<<blocks, BLOCK>>>(mailbox, W1, b1, W2, b2, out, n_nodes);
}